// round 4
// baseline (speedup 1.0000x reference)
#include <cuda_runtime.h>
#include <cuda_bf16.h>

// Problem constants
#define KSZ   9
#define PAD   4
#define H     256
#define W     256
#define HO    248
#define WO    248
#define B     4
#define PLANE (H * W)

// Tiling: block = 64x16 outputs, 256 threads, each thread a 2x2 output block.
// Warp w covers output rows 2w, 2w+1; lane covers cols 2*lane, 2*lane+1.
#define TW    64
#define TH    16
#define SW    72           // TW + 8
#define SH    24           // TH + 8
#define NTHR  256

#define GX    4            // 64*4 = 256 >= 248
#define GY    16           // 16*16 = 256 >= 248
#define NBLK  (GX * GY * B)   // 256

// -100 * log2(e) : exp(-color/0.01) = 2^(color * NC1)
#define NC1   (-144.26950408889634f)
// log2(e)/9      : dist = 2^(-d2_spatial * DC)
#define DC    (1.4426950408889634f / 9.0f)

typedef unsigned long long ull;

static __device__ float        g_bsums[NBLK];
static __device__ unsigned int g_count = 0;

__device__ __forceinline__ float ex2f(float v) {
    float r;
    asm("ex2.approx.f32 %0, %1;" : "=f"(r) : "f"(v));
    return r;
}
__device__ __forceinline__ ull pk(float lo, float hi) {
    ull r;
    asm("mov.b64 %0, {%1, %2};" : "=l"(r) : "f"(lo), "f"(hi));
    return r;
}
__device__ __forceinline__ void upk(ull v, float& lo, float& hi) {
    asm("mov.b64 {%0, %1}, %2;" : "=f"(lo), "=f"(hi) : "l"(v));
}
__device__ __forceinline__ ull f2add(ull a, ull b) {
    ull r;
    asm("add.rn.f32x2 %0, %1, %2;" : "=l"(r) : "l"(a), "l"(b));
    return r;
}
__device__ __forceinline__ ull f2mul(ull a, ull b) {
    ull r;
    asm("mul.rn.f32x2 %0, %1, %2;" : "=l"(r) : "l"(a), "l"(b));
    return r;
}
__device__ __forceinline__ ull f2fma(ull a, ull b, ull c) {
    ull r;
    asm("fma.rn.f32x2 %0, %1, %2, %3;" : "=l"(r) : "l"(a), "l"(b), "l"(c));
    return r;
}
// exp weight for a packed color pair with shared spatial constant
__device__ __forceinline__ ull wpair(ull color, float c0k) {
    float lo, hi;
    upk(color, lo, hi);
    float wl = ex2f(fmaf(lo, NC1, c0k));
    float wh = ex2f(fmaf(hi, NC1, c0k));
    return pk(wl, wh);
}

__global__ __launch_bounds__(NTHR, 2)
void potts_fused(const float* __restrict__ x, const float* __restrict__ y,
                 float* __restrict__ out) {
    __shared__ float s[5][SH][SW];   // x0,x1,x2,y0,y1 -> 34560 B

    const int b   = blockIdx.z;
    const int tx0 = blockIdx.x * TW;
    const int ty0 = blockIdx.y * TH;
    const int tid = threadIdx.x;

    const float* xb = x + (size_t)b * 3 * PLANE;
    const float* yb = y + (size_t)b * 2 * PLANE;

    // Cooperative halo load; clamp rows and cols (clamped values are consumed
    // only via zeroed y-centers of invalid outputs).
    for (int i = tid; i < 5 * SH * SW; i += NTHR) {
        int p  = i / (SH * SW);
        int r  = (i / SW) % SH;
        int c  = i % SW;
        int gy = min(ty0 + r, H - 1);
        int gx = min(tx0 + c, W - 1);
        float v = (p < 3) ? xb[p * PLANE + gy * W + gx]
                          : yb[(p - 3) * PLANE + gy * W + gx];
        s[p][r][c] = v;
    }
    __syncthreads();

    const int lane = tid & 31;
    const int w2   = (tid >> 5) * 2;     // tile-local out row (0,2,..,14)
    const int c0   = lane * 2;           // tile-local out col of out0

    const int gr0 = ty0 + w2, gr1 = gr0 + 1;
    const int gc0 = tx0 + c0, gc1 = gc0 + 1;

    // Negated x centers, packed over the column pair, per output row.
    const ull nc0_r0 = pk(-s[0][w2 + 4][c0 + 4], -s[0][w2 + 4][c0 + 5]);
    const ull nc1_r0 = pk(-s[1][w2 + 4][c0 + 4], -s[1][w2 + 4][c0 + 5]);
    const ull nc2_r0 = pk(-s[2][w2 + 4][c0 + 4], -s[2][w2 + 4][c0 + 5]);
    const ull nc0_r1 = pk(-s[0][w2 + 5][c0 + 4], -s[0][w2 + 5][c0 + 5]);
    const ull nc1_r1 = pk(-s[1][w2 + 5][c0 + 4], -s[1][w2 + 5][c0 + 5]);
    const ull nc2_r1 = pk(-s[2][w2 + 5][c0 + 4], -s[2][w2 + 5][c0 + 5]);

    // Masked y centers (zero kills invalid-output contributions entirely).
    const bool v00 = (gr0 < HO) && (gc0 < WO);
    const bool v01 = (gr0 < HO) && (gc1 < WO);
    const bool v10 = (gr1 < HO) && (gc0 < WO);
    const bool v11 = (gr1 < HO) && (gc1 < WO);
    const float y0c00 = v00 ? s[3][w2 + 4][c0 + 4] : 0.0f;
    const float y0c01 = v01 ? s[3][w2 + 4][c0 + 5] : 0.0f;
    const float y0c10 = v10 ? s[3][w2 + 5][c0 + 4] : 0.0f;
    const float y0c11 = v11 ? s[3][w2 + 5][c0 + 5] : 0.0f;
    const float y1c00 = v00 ? s[4][w2 + 4][c0 + 4] : 0.0f;
    const float y1c01 = v01 ? s[4][w2 + 4][c0 + 5] : 0.0f;
    const float y1c10 = v10 ? s[4][w2 + 5][c0 + 4] : 0.0f;
    const float y1c11 = v11 ? s[4][w2 + 5][c0 + 5] : 0.0f;

    ull aA0 = 0ull, aB0 = 0ull;   // row0: sum w*y1n, sum w*y0n (packed cols)
    ull aA1 = 0ull, aB1 = 0ull;   // row1

    #pragma unroll
    for (int R = 0; R < 10; R++) {
        const int sr = w2 + R;
        // 10-wide windows per plane, loaded as aligned float2 (conflict-free)
        float v0[10], v1[10], v2[10], q0[10], q1[10];
        #pragma unroll
        for (int m = 0; m < 5; m++) {
            float2 t;
            t = *(const float2*)&s[0][sr][c0 + 2 * m]; v0[2*m] = t.x; v0[2*m+1] = t.y;
            t = *(const float2*)&s[1][sr][c0 + 2 * m]; v1[2*m] = t.x; v1[2*m+1] = t.y;
            t = *(const float2*)&s[2][sr][c0 + 2 * m]; v2[2*m] = t.x; v2[2*m+1] = t.y;
            t = *(const float2*)&s[3][sr][c0 + 2 * m]; q0[2*m] = t.x; q0[2*m+1] = t.y;
            t = *(const float2*)&s[4][sr][c0 + 2 * m]; q1[2*m] = t.x; q1[2*m+1] = t.y;
        }
        #pragma unroll
        for (int kj = 0; kj < KSZ; kj++) {
            // Packed neighbors: shared by BOTH output rows (CSE on identical movs)
            const ull n0  = pk(v0[kj], v0[kj + 1]);
            const ull n1  = pk(v1[kj], v1[kj + 1]);
            const ull n2  = pk(v2[kj], v2[kj + 1]);
            const ull ny0 = pk(q0[kj], q0[kj + 1]);
            const ull ny1 = pk(q1[kj], q1[kj + 1]);
            const float cj2 = (float)((kj - PAD) * (kj - PAD));

            if (R <= 8) {   // out-row 0, ki = R
                const int ki = R;
                ull d0 = f2add(n0, nc0_r0);
                ull d1 = f2add(n1, nc1_r0);
                ull d2 = f2add(n2, nc2_r0);
                ull c  = f2mul(d0, d0);
                c = f2fma(d1, d1, c);
                c = f2fma(d2, d2, c);
                const float c0k = -((float)((ki - PAD) * (ki - PAD)) + cj2) * DC;
                ull wgt = wpair(c, c0k);
                aA0 = f2fma(wgt, ny1, aA0);
                aB0 = f2fma(wgt, ny0, aB0);
            }
            if (R >= 1) {   // out-row 1, ki = R-1
                const int ki = R - 1;
                ull d0 = f2add(n0, nc0_r1);
                ull d1 = f2add(n1, nc1_r1);
                ull d2 = f2add(n2, nc2_r1);
                ull c  = f2mul(d0, d0);
                c = f2fma(d1, d1, c);
                c = f2fma(d2, d2, c);
                const float c0k = -((float)((ki - PAD) * (ki - PAD)) + cj2) * DC;
                ull wgt = wpair(c, c0k);
                aA1 = f2fma(wgt, ny1, aA1);
                aB1 = f2fma(wgt, ny0, aB1);
            }
        }
    }

    float a0l, a0h, b0l, b0h, a1l, a1h, b1l, b1h;
    upk(aA0, a0l, a0h); upk(aB0, b0l, b0h);
    upk(aA1, a1l, a1h); upk(aB1, b1l, b1h);
    float acc = fmaf(y0c00, a0l, fmaf(y1c00, b0l,
                fmaf(y0c01, a0h, fmaf(y1c01, b0h,
                fmaf(y0c10, a1l, fmaf(y1c10, b1l,
                fmaf(y0c11, a1h, y1c11 * b1h)))))));

    // Deterministic block reduction
    #pragma unroll
    for (int off = 16; off > 0; off >>= 1)
        acc += __shfl_down_sync(0xffffffffu, acc, off);

    __shared__ float wsum[NTHR / 32];
    if (lane == 0) wsum[tid >> 5] = acc;
    __syncthreads();

    __shared__ bool is_last;
    if (tid == 0) {
        float t = 0.0f;
        #pragma unroll
        for (int i = 0; i < NTHR / 32; i++) t += wsum[i];
        const int bid = blockIdx.x + GX * (blockIdx.y + GY * blockIdx.z);
        g_bsums[bid] = t;
        __threadfence();
        unsigned int old = atomicAdd(&g_count, 1u);
        is_last = (old == (unsigned)(NBLK - 1));
    }
    __syncthreads();

    if (is_last) {
        __threadfence();
        double dacc = 0.0;
        for (int i = tid; i < NBLK; i += NTHR) dacc += (double)g_bsums[i];
        #pragma unroll
        for (int off = 16; off > 0; off >>= 1)
            dacc += __shfl_down_sync(0xffffffffu, dacc, off);
        __shared__ double dsum[NTHR / 32];
        if (lane == 0) dsum[tid >> 5] = dacc;
        __syncthreads();
        if (tid == 0) {
            double t = 0.0;
            #pragma unroll
            for (int i = 0; i < NTHR / 32; i++) t += dsum[i];
            const double scale = 1.0 / ((double)B * 81.0 * (double)HO * (double)WO);
            out[0] = (float)(t * scale);
            g_count = 0;   // reset for next graph replay
        }
    }
}

extern "C" void kernel_launch(void* const* d_in, const int* in_sizes, int n_in,
                              void* d_out, int out_size) {
    const float* x = (const float*)d_in[0];   // [4,3,256,256]
    const float* y = (const float*)d_in[1];   // [4,2,256,256]
    float* out = (float*)d_out;

    dim3 grid(GX, GY, B);
    potts_fused<<<grid, NTHR>>>(x, y, out);
}

// round 5
// speedup vs baseline: 1.0622x; 1.0622x over previous
#include <cuda_runtime.h>
#include <cuda_bf16.h>

// Problem constants
#define KSZ   9
#define PAD   4
#define H     256
#define W     256
#define HO    248
#define WO    248
#define B     4
#define PLANE (H * W)

// Tiling: each block computes a 64x8 output tile; warp = one row, 2 cols/lane.
#define TW    64
#define TH    8
#define SW    (TW + 8)     // 72
#define SH    (TH + 8)     // 16
#define NTHR  256

#define GX    4            // ceil(248/64)
#define GY    31
#define NBLK  (GX * GY * B)   // 496

// -100 * log2(e)  : exp(-color/0.01) = 2^(color * NC1)
#define NC1   (-144.26950408889634f)
// log2(e)/9       : dist = 2^(-d2_spatial * DC)
#define DC    (1.4426950408889634f / 9.0f)

typedef unsigned long long ull;

static __device__ float        g_bsums[NBLK];
static __device__ unsigned int g_count = 0;

__device__ __forceinline__ float ex2f(float v) {
    float r;
    asm("ex2.approx.f32 %0, %1;" : "=f"(r) : "f"(v));
    return r;
}
__device__ __forceinline__ ull pk(float lo, float hi) {
    ull r;
    asm("mov.b64 %0, {%1, %2};" : "=l"(r) : "f"(lo), "f"(hi));
    return r;
}
__device__ __forceinline__ void upk(ull v, float& lo, float& hi) {
    asm("mov.b64 {%0, %1}, %2;" : "=f"(lo), "=f"(hi) : "l"(v));
}
__device__ __forceinline__ ull f2add(ull a, ull b) {
    ull r;
    asm("add.rn.f32x2 %0, %1, %2;" : "=l"(r) : "l"(a), "l"(b));
    return r;
}
__device__ __forceinline__ ull f2mul(ull a, ull b) {
    ull r;
    asm("mul.rn.f32x2 %0, %1, %2;" : "=l"(r) : "l"(a), "l"(b));
    return r;
}
__device__ __forceinline__ ull f2fma(ull a, ull b, ull c) {
    ull r;
    asm("fma.rn.f32x2 %0, %1, %2, %3;" : "=l"(r) : "l"(a), "l"(b), "l"(c));
    return r;
}

// 4 blocks/SM: 32 warps resident, regs capped at 64 (R2 build used 62).
__global__ __launch_bounds__(NTHR, 4)
void potts_fused(const float* __restrict__ x, const float* __restrict__ y,
                 float* __restrict__ out) {
    __shared__ float s[5][SH][SW];   // x0,x1,x2,y0,y1 -> 23040 B

    const int b   = blockIdx.z;
    const int tx0 = blockIdx.x * TW;
    const int ty0 = blockIdx.y * TH;
    const int tid = threadIdx.x;

    const float* xb = x + (size_t)b * 3 * PLANE;
    const float* yb = y + (size_t)b * 2 * PLANE;

    // Cooperative halo load. Rows always in [0,256); cols clamped (consumed
    // only through zeroed centers for invalid outputs).
    for (int i = tid; i < 5 * SH * SW; i += NTHR) {
        int p  = i / (SH * SW);
        int r  = (i / SW) % SH;
        int c  = i % SW;
        int gy = ty0 + r;
        int gx = min(tx0 + c, W - 1);
        float v = (p < 3) ? xb[p * PLANE + gy * W + gx]
                          : yb[(p - 3) * PLANE + gy * W + gx];
        s[p][r][c] = v;
    }
    __syncthreads();

    const int lane = tid & 31;
    const int ly   = tid >> 5;          // 0..7
    const int lx2  = lane * 2;          // tile-local col of out0
    const int col0 = tx0 + lx2;
    const bool v0  = (col0 < WO);
    const bool v1  = (col0 + 1 < WO);

    // Negated centers, packed (out0, out1)
    const ull negc0 = pk(-s[0][ly + PAD][lx2 + PAD], -s[0][ly + PAD][lx2 + 1 + PAD]);
    const ull negc1 = pk(-s[1][ly + PAD][lx2 + PAD], -s[1][ly + PAD][lx2 + 1 + PAD]);
    const ull negc2 = pk(-s[2][ly + PAD][lx2 + PAD], -s[2][ly + PAD][lx2 + 1 + PAD]);
    // Mask centers (zeroing kills contributions from invalid columns)
    const float y0c0 = v0 ? s[3][ly + PAD][lx2 + PAD]     : 0.0f;
    const float y0c1 = v1 ? s[3][ly + PAD][lx2 + 1 + PAD] : 0.0f;
    const float y1c0 = v0 ? s[4][ly + PAD][lx2 + PAD]     : 0.0f;
    const float y1c1 = v1 ? s[4][ly + PAD][lx2 + 1 + PAD] : 0.0f;

    ull accA = 0ull;   // packed Sum w * y1_neighbor
    ull accB = 0ull;   // packed Sum w * y0_neighbor

    #pragma unroll
    for (int ki = 0; ki < KSZ; ki++) {
        const int row = ly + ki;
        // Load 10 contiguous floats per plane as 5x float2 (8B aligned)
        float vx0[10], vx1[10], vx2[10], vy0[10], vy1[10];
        #pragma unroll
        for (int m = 0; m < 5; m++) {
            float2 t;
            t = *(const float2*)&s[0][row][lx2 + 2 * m]; vx0[2*m] = t.x; vx0[2*m+1] = t.y;
            t = *(const float2*)&s[1][row][lx2 + 2 * m]; vx1[2*m] = t.x; vx1[2*m+1] = t.y;
            t = *(const float2*)&s[2][row][lx2 + 2 * m]; vx2[2*m] = t.x; vx2[2*m+1] = t.y;
            t = *(const float2*)&s[3][row][lx2 + 2 * m]; vy0[2*m] = t.x; vy0[2*m+1] = t.y;
            t = *(const float2*)&s[4][row][lx2 + 2 * m]; vy1[2*m] = t.x; vy1[2*m+1] = t.y;
        }
        #pragma unroll
        for (int kj = 0; kj < KSZ; kj++) {
            ull n0 = pk(vx0[kj], vx0[kj + 1]);
            ull n1 = pk(vx1[kj], vx1[kj + 1]);
            ull n2 = pk(vx2[kj], vx2[kj + 1]);
            ull d0 = f2add(n0, negc0);
            ull d1 = f2add(n1, negc1);
            ull d2 = f2add(n2, negc2);
            ull c  = f2mul(d0, d0);
            c = f2fma(d1, d1, c);
            c = f2fma(d2, d2, c);
            float clo, chi;
            upk(c, clo, chi);
            const float c0k = -(float)((ki - PAD) * (ki - PAD) +
                                       (kj - PAD) * (kj - PAD)) * DC;
            float wlo = ex2f(fmaf(clo, NC1, c0k));
            float whi = ex2f(fmaf(chi, NC1, c0k));
            ull w = pk(wlo, whi);
            accA = f2fma(w, pk(vy1[kj], vy1[kj + 1]), accA);
            accB = f2fma(w, pk(vy0[kj], vy0[kj + 1]), accB);
        }
    }

    float a0, a1, b0, b1;
    upk(accA, a0, a1);
    upk(accB, b0, b1);
    float acc = fmaf(y0c0, a0, fmaf(y1c0, b0, fmaf(y0c1, a1, y1c1 * b1)));

    // Deterministic block reduction
    #pragma unroll
    for (int off = 16; off > 0; off >>= 1)
        acc += __shfl_down_sync(0xffffffffu, acc, off);

    __shared__ float wsum[NTHR / 32];
    if (lane == 0) wsum[ly] = acc;
    __syncthreads();

    __shared__ bool is_last;
    if (tid == 0) {
        float t = 0.0f;
        #pragma unroll
        for (int i = 0; i < NTHR / 32; i++) t += wsum[i];
        const int bid = blockIdx.x + GX * (blockIdx.y + GY * blockIdx.z);
        g_bsums[bid] = t;
        __threadfence();
        unsigned int old = atomicAdd(&g_count, 1u);
        is_last = (old == (unsigned)(NBLK - 1));
    }
    __syncthreads();

    if (is_last) {
        __threadfence();
        double dacc = 0.0;
        for (int i = tid; i < NBLK; i += NTHR) dacc += (double)g_bsums[i];
        #pragma unroll
        for (int off = 16; off > 0; off >>= 1)
            dacc += __shfl_down_sync(0xffffffffu, dacc, off);
        __shared__ double dsum[NTHR / 32];
        if (lane == 0) dsum[tid >> 5] = dacc;
        __syncthreads();
        if (tid == 0) {
            double t = 0.0;
            #pragma unroll
            for (int i = 0; i < NTHR / 32; i++) t += dsum[i];
            const double scale = 1.0 / ((double)B * 81.0 * (double)HO * (double)WO);
            out[0] = (float)(t * scale);
            g_count = 0;   // reset for next graph replay
        }
    }
}

extern "C" void kernel_launch(void* const* d_in, const int* in_sizes, int n_in,
                              void* d_out, int out_size) {
    const float* x = (const float*)d_in[0];   // [4,3,256,256]
    const float* y = (const float*)d_in[1];   // [4,2,256,256]
    float* out = (float*)d_out;

    dim3 grid(GX, GY, B);
    potts_fused<<<grid, NTHR>>>(x, y, out);
}